// round 3
// baseline (speedup 1.0000x reference)
#include <cuda_runtime.h>

// Scratch: xW = x @ W[64:192] + b   (50000 x 128 f32 = 25.6 MB, L2-resident)
#define MAX_NODES 50000
__device__ float g_xw[(size_t)MAX_NODES * 128];

typedef unsigned long long u64;

__device__ __forceinline__ void ffma2(u64& acc, u64 a, u64 w) {
    asm("fma.rn.f32x2 %0, %1, %2, %0;" : "+l"(acc) : "l"(a), "l"(w));
}
__device__ __forceinline__ u64 dup2(float v) {
    u64 d; asm("mov.b64 %0, {%1, %1};" : "=l"(d) : "f"(v)); return d;
}
__device__ __forceinline__ float2 unpk(u64 d) {
    float2 r; asm("mov.b64 {%0, %1}, %2;" : "=f"(r.x), "=f"(r.y) : "l"(d)); return r;
}
__device__ __forceinline__ void red_add_v4(float* p, float a, float b, float c, float d) {
    asm volatile("red.global.add.v4.f32 [%0], {%1,%2,%3,%4};"
                 :: "l"(p), "f"(a), "f"(b), "f"(c), "f"(d) : "memory");
}

// ---------------------------------------------------------------------------
// Kernel 1: node precompute  xW[n][o] = b[o] + sum_k x[n][k] * W[64+k][o]
// 128x128 tile, 256 threads, f32x2 packed FMA, K in 2 chunks of 64.
// smem: W_s [64][128] f32 (32KB) + x2 [64][128] dup-f32x2 swizzled (64KB)
// ---------------------------------------------------------------------------
__global__ __launch_bounds__(256, 2)
void node_xw_kernel(const float* __restrict__ x,
                    const float* __restrict__ W,   // [192][128]
                    const float* __restrict__ b,
                    int N) {
    extern __shared__ float sm[];
    float* W_s = sm;                       // 8192 floats
    u64*   x2  = (u64*)(sm + 8192);        // 8192 u64 (64 k x 128 nodes)

    const int tid = threadIdx.x;
    const int tx = tid & 15, ty = tid >> 4;
    const int n0 = blockIdx.x * 128;

    u64 acc[8][4];
#pragma unroll
    for (int i = 0; i < 8; i++)
#pragma unroll
        for (int j = 0; j < 4; j++) acc[i][j] = 0ull;

    for (int kc = 0; kc < 2; kc++) {
        __syncthreads();
        // W chunk rows [64 + kc*64, +64)
#pragma unroll
        for (int it = 0; it < 8; it++) {
            int i = tid + it * 256;
            int k = i >> 5, oq = i & 31;
            *(float4*)&W_s[k * 128 + oq * 4] =
                *(const float4*)&W[(size_t)(64 + kc * 64 + k) * 128 + oq * 4];
        }
        // x chunk -> duplicated swizzled transpose x2[k][node]
#pragma unroll
        for (int it = 0; it < 8; it++) {
            int i = tid + it * 256;
            int n = i >> 4, kq = i & 15;
            float4 v = make_float4(0.f, 0.f, 0.f, 0.f);
            if (n0 + n < N)
                v = *(const float4*)&x[(size_t)(n0 + n) * 128 + kc * 64 + kq * 4];
            int cs = (((n >> 1) ^ kq) << 1) + (n & 1);
            u64* row = x2 + (kq * 4) * 128 + cs;
            row[0]   = dup2(v.x);
            row[128] = dup2(v.y);
            row[256] = dup2(v.z);
            row[384] = dup2(v.w);
        }
        __syncthreads();

#pragma unroll 4
        for (int k = 0; k < 64; k++) {
            int kq = k >> 2;
            const u64* base = x2 + k * 128;
            ulonglong2 aA0 = *(const ulonglong2*)(base + ((( 2*ty    ) ^ kq) << 1));
            ulonglong2 aA1 = *(const ulonglong2*)(base + ((( 2*ty + 1) ^ kq) << 1));
            ulonglong2 aB0 = *(const ulonglong2*)(base + (((32 + 2*ty) ^ kq) << 1));
            ulonglong2 aB1 = *(const ulonglong2*)(base + (((33 + 2*ty) ^ kq) << 1));
            ulonglong2 w0 = *(const ulonglong2*)&W_s[k * 128 + tx * 4];
            ulonglong2 w1 = *(const ulonglong2*)&W_s[k * 128 + 64 + tx * 4];
            u64 a2[8] = {aA0.x, aA0.y, aA1.x, aA1.y, aB0.x, aB0.y, aB1.x, aB1.y};
#pragma unroll
            for (int i = 0; i < 8; i++) {
                ffma2(acc[i][0], a2[i], w0.x);
                ffma2(acc[i][1], a2[i], w0.y);
                ffma2(acc[i][2], a2[i], w1.x);
                ffma2(acc[i][3], a2[i], w1.y);
            }
        }
    }

    float4 b0 = *(const float4*)&b[tx * 4];
    float4 b1 = *(const float4*)&b[64 + tx * 4];
#pragma unroll
    for (int i = 0; i < 8; i++) {
        int n = (i < 4) ? (ty * 4 + i) : (64 + ty * 4 + (i - 4));
        if (n0 + n >= N) continue;
        float2 p0 = unpk(acc[i][0]), p1 = unpk(acc[i][1]);
        float2 p2 = unpk(acc[i][2]), p3 = unpk(acc[i][3]);
        float* p = &g_xw[(size_t)(n0 + n) * 128];
        *(float4*)&p[tx * 4] =
            make_float4(p0.x + b0.x, p0.y + b0.y, p1.x + b0.z, p1.y + b0.w);
        *(float4*)&p[64 + tx * 4] =
            make_float4(p2.x + b1.x, p2.y + b1.y, p3.x + b1.z, p3.y + b1.w);
    }
}

// ---------------------------------------------------------------------------
// Kernel 2: edge GEMM (K=64, f32x2 packed) + gather xW[src] + ReLU + scatter
// smem: W_s [64][128] (32KB) + ea2 [64][128] dup-f32x2 swizzled (64KB) + idx
// ---------------------------------------------------------------------------
__global__ __launch_bounds__(256, 2)
void edge_kernel(const int* __restrict__ eidx,  // [2][E] int32
                 const float* __restrict__ ea,  // [E][64]
                 const float* __restrict__ W,   // [192][128]
                 float* __restrict__ out,       // [N][128]
                 int E, int N) {
    extern __shared__ float sm[];
    float* W_s = sm;                       // 8192 floats
    u64*   ea2 = (u64*)(sm + 8192);        // 8192 u64
    int*   src_s = (int*)(sm + 8192 + 16384);
    int*   dst_s = src_s + 128;

    const int tid = threadIdx.x;
    const int tx = tid & 15, ty = tid >> 4;
    const int e0 = blockIdx.x * 128;

    // W rows 0..63 (edge part)
#pragma unroll
    for (int it = 0; it < 8; it++) {
        int i = tid + it * 256;
        int k = i >> 5, oq = i & 31;
        *(float4*)&W_s[k * 128 + oq * 4] =
            *(const float4*)&W[(size_t)k * 128 + oq * 4];
    }
    // edge_attr tile -> duplicated swizzled transpose ea2[k][edge]
#pragma unroll
    for (int it = 0; it < 8; it++) {
        int i = tid + it * 256;
        int e = i >> 4, kq = i & 15;
        float4 v = make_float4(0.f, 0.f, 0.f, 0.f);
        if (e0 + e < E)
            v = *(const float4*)&ea[(size_t)(e0 + e) * 64 + kq * 4];
        int cs = (((e >> 1) ^ kq) << 1) + (e & 1);
        u64* row = ea2 + (kq * 4) * 128 + cs;
        row[0]   = dup2(v.x);
        row[128] = dup2(v.y);
        row[256] = dup2(v.z);
        row[384] = dup2(v.w);
    }
    if (tid < 128) {
        int e = e0 + tid;
        src_s[tid] = (e < E) ? eidx[e] : -1;
        dst_s[tid] = (e < E) ? eidx[(size_t)E + e] : -1;
    }
    __syncthreads();

    u64 acc[8][4];
#pragma unroll
    for (int i = 0; i < 8; i++)
#pragma unroll
        for (int j = 0; j < 4; j++) acc[i][j] = 0ull;

#pragma unroll 4
    for (int k = 0; k < 64; k++) {
        int kq = k >> 2;
        const u64* base = ea2 + k * 128;
        ulonglong2 aA0 = *(const ulonglong2*)(base + ((( 2*ty    ) ^ kq) << 1));
        ulonglong2 aA1 = *(const ulonglong2*)(base + ((( 2*ty + 1) ^ kq) << 1));
        ulonglong2 aB0 = *(const ulonglong2*)(base + (((32 + 2*ty) ^ kq) << 1));
        ulonglong2 aB1 = *(const ulonglong2*)(base + (((33 + 2*ty) ^ kq) << 1));
        ulonglong2 w0 = *(const ulonglong2*)&W_s[k * 128 + tx * 4];
        ulonglong2 w1 = *(const ulonglong2*)&W_s[k * 128 + 64 + tx * 4];
        u64 a2[8] = {aA0.x, aA0.y, aA1.x, aA1.y, aB0.x, aB0.y, aB1.x, aB1.y};
#pragma unroll
        for (int i = 0; i < 8; i++) {
            ffma2(acc[i][0], a2[i], w0.x);
            ffma2(acc[i][1], a2[i], w0.y);
            ffma2(acc[i][2], a2[i], w1.x);
            ffma2(acc[i][3], a2[i], w1.y);
        }
    }

    // epilogue: gather xW[src] (L2-resident), ReLU, vector atomic scatter
#pragma unroll
    for (int i = 0; i < 8; i++) {
        int le = (i < 4) ? (ty * 4 + i) : (64 + ty * 4 + (i - 4));
        if (e0 + le >= E) continue;
        int s = src_s[le];
        int d = dst_s[le];
        if ((unsigned)s >= (unsigned)N || (unsigned)d >= (unsigned)N) continue;
        const float* gp = &g_xw[(size_t)s * 128];
        float4 g0 = *(const float4*)&gp[tx * 4];
        float4 g1 = *(const float4*)&gp[64 + tx * 4];
        float2 p0 = unpk(acc[i][0]), p1 = unpk(acc[i][1]);
        float2 p2 = unpk(acc[i][2]), p3 = unpk(acc[i][3]);
        float* op = &out[(size_t)d * 128];
        red_add_v4(&op[tx * 4],
                   fmaxf(p0.x + g0.x, 0.f), fmaxf(p0.y + g0.y, 0.f),
                   fmaxf(p1.x + g0.z, 0.f), fmaxf(p1.y + g0.w, 0.f));
        red_add_v4(&op[64 + tx * 4],
                   fmaxf(p2.x + g1.x, 0.f), fmaxf(p2.y + g1.y, 0.f),
                   fmaxf(p3.x + g1.z, 0.f), fmaxf(p3.y + g1.w, 0.f));
    }
}

extern "C" void kernel_launch(void* const* d_in, const int* in_sizes, int n_in,
                              void* d_out, int out_size) {
    const float* x    = (const float*)d_in[0];
    const int*   eidx = (const int*)d_in[1];   // int32 [2][E]
    const float* ea   = (const float*)d_in[2];
    const float* W    = (const float*)d_in[3];
    const float* b    = (const float*)d_in[4];
    float* out = (float*)d_out;

    const int N = in_sizes[0] / 128;   // 50000
    const int E = in_sizes[2] / 64;    // 800000

    const int node_smem = 8192 * 4 + 8192 * 8;              // 96 KB
    const int edge_smem = 8192 * 4 + 8192 * 8 + 256 * 4;    // 96 KB + idx

    cudaFuncSetAttribute(node_xw_kernel,
                         cudaFuncAttributeMaxDynamicSharedMemorySize, node_smem);
    cudaFuncSetAttribute(edge_kernel,
                         cudaFuncAttributeMaxDynamicSharedMemorySize, edge_smem);

    cudaMemsetAsync(d_out, 0, (size_t)out_size * sizeof(float), 0);

    node_xw_kernel<<<(N + 127) / 128, 256, node_smem>>>(x, W, b, N);
    edge_kernel<<<(E + 127) / 128, 256, edge_smem>>>(eidx, ea, W, out, E, N);
}

// round 5
// speedup vs baseline: 1.3576x; 1.3576x over previous
#include <cuda_runtime.h>
#include <cstdint>

#define MAX_NODES 50000
__device__ float    g_xw[(size_t)MAX_NODES * 128];   // x @ W[64:192] + b (fp32)
__device__ uint2    g_wt2[8 * 128 * 4];              // W[0:64] tf32, packed frags

typedef unsigned long long u64;

// ---------------- helpers ----------------
__device__ __forceinline__ void ffma2(u64& acc, u64 a, u64 w) {
    asm("fma.rn.f32x2 %0, %1, %2, %0;" : "+l"(acc) : "l"(a), "l"(w));
}
__device__ __forceinline__ u64 dup2(float v) {
    u64 d; asm("mov.b64 %0, {%1, %1};" : "=l"(d) : "f"(v)); return d;
}
__device__ __forceinline__ float2 unpk(u64 d) {
    float2 r; asm("mov.b64 {%0, %1}, %2;" : "=f"(r.x), "=f"(r.y) : "l"(d)); return r;
}
__device__ __forceinline__ void red_add_v4(float* p, float a, float b, float c, float d) {
    asm volatile("red.global.add.v4.f32 [%0], {%1,%2,%3,%4};"
                 :: "l"(p), "f"(a), "f"(b), "f"(c), "f"(d) : "memory");
}
__device__ __forceinline__ uint32_t tf32r(float f) {
    uint32_t r; asm("cvt.rna.tf32.f32 %0, %1;" : "=r"(r) : "f"(f)); return r;
}
__device__ __forceinline__ void mma_tf32(float& c0, float& c1, float& c2, float& c3,
                                         uint32_t a0, uint32_t a1, uint32_t a2, uint32_t a3,
                                         uint32_t b0, uint32_t b1) {
    asm volatile("mma.sync.aligned.m16n8k8.row.col.f32.tf32.tf32.f32 "
                 "{%0,%1,%2,%3}, {%4,%5,%6,%7}, {%8,%9}, {%0,%1,%2,%3};"
                 : "+f"(c0), "+f"(c1), "+f"(c2), "+f"(c3)
                 : "r"(a0), "r"(a1), "r"(a2), "r"(a3), "r"(b0), "r"(b1));
}

// ---------------------------------------------------------------------------
// Kernel 0: prep W[0:64] into mma B-fragment layout, tf32, column-permuted.
// g_wt2[kstep*512 + n_phys*4 + c] = (tf32 W[kstep*8+c][L(n)], tf32 W[kstep*8+c+4][L(n)])
// Logical column L(n): perm so each thread's 4 output cols are contiguous.
// ---------------------------------------------------------------------------
__global__ void wt_prep_kernel(const float* __restrict__ W) {
    int i = blockIdx.x * 256 + threadIdx.x;   // 4096 entries
    if (i >= 4096) return;
    int kstep = i >> 9;
    int n     = (i >> 2) & 127;
    int c     = i & 3;
    int q = n & 15;
    int l;
    if (q < 8) l = (n & ~15) + 4 * (q >> 1) + (q & 1);
    else       l = (n & ~15) + 4 * ((q - 8) >> 1) + 2 + (q & 1);
    int k0 = kstep * 8 + c;
    g_wt2[i] = make_uint2(tf32r(W[(size_t)k0 * 128 + l]),
                          tf32r(W[(size_t)(k0 + 4) * 128 + l]));
}

// ---------------------------------------------------------------------------
// Kernel 1: node precompute  xW = x @ W[64:192] + b  (fp32, f32x2 FMA)
// ---------------------------------------------------------------------------
__global__ __launch_bounds__(256, 2)
void node_xw_kernel(const float* __restrict__ x,
                    const float* __restrict__ W,   // [192][128]
                    const float* __restrict__ b,
                    int N) {
    extern __shared__ float sm[];
    float* W_s = sm;                       // 8192 floats
    u64*   x2  = (u64*)(sm + 8192);        // 8192 u64

    const int tid = threadIdx.x;
    const int tx = tid & 15, ty = tid >> 4;
    const int n0 = blockIdx.x * 128;

    u64 acc[8][4];
#pragma unroll
    for (int i = 0; i < 8; i++)
#pragma unroll
        for (int j = 0; j < 4; j++) acc[i][j] = 0ull;

    for (int kc = 0; kc < 2; kc++) {
        __syncthreads();
#pragma unroll
        for (int it = 0; it < 8; it++) {
            int i = tid + it * 256;
            int k = i >> 5, oq = i & 31;
            *(float4*)&W_s[k * 128 + oq * 4] =
                *(const float4*)&W[(size_t)(64 + kc * 64 + k) * 128 + oq * 4];
        }
#pragma unroll
        for (int it = 0; it < 8; it++) {
            int i = tid + it * 256;
            int n = i >> 4, kq = i & 15;
            float4 v = make_float4(0.f, 0.f, 0.f, 0.f);
            if (n0 + n < N)
                v = *(const float4*)&x[(size_t)(n0 + n) * 128 + kc * 64 + kq * 4];
            int cs = (((n >> 1) ^ kq) << 1) + (n & 1);
            u64* row = x2 + (kq * 4) * 128 + cs;
            row[0]   = dup2(v.x);
            row[128] = dup2(v.y);
            row[256] = dup2(v.z);
            row[384] = dup2(v.w);
        }
        __syncthreads();

#pragma unroll 4
        for (int k = 0; k < 64; k++) {
            int kq = k >> 2;
            const u64* base = x2 + k * 128;
            ulonglong2 aA0 = *(const ulonglong2*)(base + ((( 2*ty    ) ^ kq) << 1));
            ulonglong2 aA1 = *(const ulonglong2*)(base + ((( 2*ty + 1) ^ kq) << 1));
            ulonglong2 aB0 = *(const ulonglong2*)(base + (((32 + 2*ty) ^ kq) << 1));
            ulonglong2 aB1 = *(const ulonglong2*)(base + (((33 + 2*ty) ^ kq) << 1));
            ulonglong2 w0 = *(const ulonglong2*)&W_s[k * 128 + tx * 4];
            ulonglong2 w1 = *(const ulonglong2*)&W_s[k * 128 + 64 + tx * 4];
            u64 a2[8] = {aA0.x, aA0.y, aA1.x, aA1.y, aB0.x, aB0.y, aB1.x, aB1.y};
#pragma unroll
            for (int i = 0; i < 8; i++) {
                ffma2(acc[i][0], a2[i], w0.x);
                ffma2(acc[i][1], a2[i], w0.y);
                ffma2(acc[i][2], a2[i], w1.x);
                ffma2(acc[i][3], a2[i], w1.y);
            }
        }
    }

    float4 b0 = *(const float4*)&b[tx * 4];
    float4 b1 = *(const float4*)&b[64 + tx * 4];
#pragma unroll
    for (int i = 0; i < 8; i++) {
        int n = (i < 4) ? (ty * 4 + i) : (64 + ty * 4 + (i - 4));
        if (n0 + n >= N) continue;
        float2 p0 = unpk(acc[i][0]), p1 = unpk(acc[i][1]);
        float2 p2 = unpk(acc[i][2]), p3 = unpk(acc[i][3]);
        float* p = &g_xw[(size_t)(n0 + n) * 128];
        *(float4*)&p[tx * 4] =
            make_float4(p0.x + b0.x, p0.y + b0.y, p1.x + b0.z, p1.y + b0.w);
        *(float4*)&p[64 + tx * 4] =
            make_float4(p2.x + b1.x, p2.y + b1.y, p3.x + b1.z, p3.y + b1.w);
    }
}

// ---------------------------------------------------------------------------
// Kernel 2: edge GEMM via mma.sync tf32 + gather + ReLU + atomic scatter
// A_s: [64 k][136 floats] tf32, edge index XOR-swizzled by (k>>2)&7
// B_s: copy of g_wt2 [kstep][n][c] uint2 (32 KB)
// Warp w = edges [16w, 16w+16); 16 n-tiles; 8 k-steps.
// ---------------------------------------------------------------------------
#define A_PITCH 136
#define A_BYTES (64 * A_PITCH * 4)          // 34816
#define B_OFF   A_BYTES                     // 34816
#define B_BYTES 32768
#define IDX_OFF (A_BYTES + B_BYTES)         // 67584
#define EDGE_SMEM (IDX_OFF + 1024)          // 68608

__global__ __launch_bounds__(256, 2)
void edge_mma_kernel(const int* __restrict__ eidx,   // [2][E] int32
                     const float* __restrict__ ea,   // [E][64]
                     float* __restrict__ out,        // [N][128]
                     int E, int N) {
    extern __shared__ char smem[];
    float* A_s = (float*)smem;
    uint2* B_s = (uint2*)(smem + B_OFF);
    int*   src_s = (int*)(smem + IDX_OFF);
    int*   dst_s = src_s + 128;

    const int tid  = threadIdx.x;
    const int wid  = tid >> 5, lane = tid & 31;
    const int g    = lane >> 2, t = lane & 3;
    const int e0   = blockIdx.x * 128;

    // stage A: edge_attr -> tf32, k-major swizzled
#pragma unroll
    for (int it = 0; it < 8; it++) {
        int i = tid + it * 256;          // 2048 float4
        int e = i >> 4, kq = i & 15;
        float4 v = make_float4(0.f, 0.f, 0.f, 0.f);
        if (e0 + e < E)
            v = *(const float4*)&ea[(size_t)(e0 + e) * 64 + kq * 4];
        int es = e ^ (kq & 7);
        A_s[(4 * kq + 0) * A_PITCH + es] = __uint_as_float(tf32r(v.x));
        A_s[(4 * kq + 1) * A_PITCH + es] = __uint_as_float(tf32r(v.y));
        A_s[(4 * kq + 2) * A_PITCH + es] = __uint_as_float(tf32r(v.z));
        A_s[(4 * kq + 3) * A_PITCH + es] = __uint_as_float(tf32r(v.w));
    }
    // stage B: copy packed weights (L2-resident, 32 KB)
    {
        const uint4* src = (const uint4*)g_wt2;
        uint4* dst = (uint4*)B_s;
#pragma unroll
        for (int it = 0; it < 8; it++)
            dst[tid + it * 256] = src[tid + it * 256];
    }
    if (tid < 128) {
        int e = e0 + tid;
        src_s[tid] = (e < E) ? eidx[e] : -1;
        dst_s[tid] = (e < E) ? eidx[(size_t)E + e] : -1;
    }
    __syncthreads();

    float acc[16][4];
#pragma unroll
    for (int nt = 0; nt < 16; nt++)
#pragma unroll
        for (int j = 0; j < 4; j++) acc[nt][j] = 0.0f;

    const int wbase = wid * 16;
#pragma unroll
    for (int ks = 0; ks < 8; ks++) {
        int q02 = (ks * 2) & 7;
        int q13 = (ks * 2 + 1) & 7;
        uint32_t a0 = __float_as_uint(A_s[(ks * 8 + t)     * A_PITCH + ((wbase + g)     ^ q02)]);
        uint32_t a1 = __float_as_uint(A_s[(ks * 8 + t)     * A_PITCH + ((wbase + 8 + g) ^ q02)]);
        uint32_t a2 = __float_as_uint(A_s[(ks * 8 + t + 4) * A_PITCH + ((wbase + g)     ^ q13)]);
        uint32_t a3 = __float_as_uint(A_s[(ks * 8 + t + 4) * A_PITCH + ((wbase + 8 + g) ^ q13)]);
        const uint2* brow = B_s + ks * 512 + g * 4 + t;
#pragma unroll
        for (int nt = 0; nt < 16; nt++) {
            uint2 b = brow[nt * 32];
            mma_tf32(acc[nt][0], acc[nt][1], acc[nt][2], acc[nt][3],
                     a0, a1, a2, a3, b.x, b.y);
        }
    }

    // epilogue: per thread 2 edge-rows x 8 column-quads (logical cols contiguous)
#pragma unroll
    for (int rs = 0; rs < 2; rs++) {
        int m = wbase + g + 8 * rs;
        int s = src_s[m];
        int d = dst_s[m];
        if (e0 + m >= E || (unsigned)s >= (unsigned)N || (unsigned)d >= (unsigned)N)
            continue;
        const float* gp = &g_xw[(size_t)s * 128];
        float* op = &out[(size_t)d * 128];
#pragma unroll
        for (int p = 0; p < 8; p++) {
            int lc = p * 16 + 4 * t;
            float4 gv = *(const float4*)&gp[lc];
            float v0 = fmaxf(acc[2 * p    ][rs * 2    ] + gv.x, 0.f);
            float v1 = fmaxf(acc[2 * p    ][rs * 2 + 1] + gv.y, 0.f);
            float v2 = fmaxf(acc[2 * p + 1][rs * 2    ] + gv.z, 0.f);
            float v3 = fmaxf(acc[2 * p + 1][rs * 2 + 1] + gv.w, 0.f);
            red_add_v4(op + lc, v0, v1, v2, v3);
        }
    }
}

extern "C" void kernel_launch(void* const* d_in, const int* in_sizes, int n_in,
                              void* d_out, int out_size) {
    const float* x    = (const float*)d_in[0];
    const int*   eidx = (const int*)d_in[1];   // int32 [2][E]
    const float* ea   = (const float*)d_in[2];
    const float* W    = (const float*)d_in[3];
    const float* b    = (const float*)d_in[4];
    float* out = (float*)d_out;

    const int N = in_sizes[0] / 128;   // 50000
    const int E = in_sizes[2] / 64;    // 800000

    const int node_smem = 8192 * 4 + 8192 * 8;   // 96 KB

    cudaFuncSetAttribute(node_xw_kernel,
                         cudaFuncAttributeMaxDynamicSharedMemorySize, node_smem);
    cudaFuncSetAttribute(edge_mma_kernel,
                         cudaFuncAttributeMaxDynamicSharedMemorySize, EDGE_SMEM);

    cudaMemsetAsync(d_out, 0, (size_t)out_size * sizeof(float), 0);

    wt_prep_kernel<<<16, 256>>>(W);
    node_xw_kernel<<<(N + 127) / 128, 256, node_smem>>>(x, W, b, N);
    edge_mma_kernel<<<(E + 127) / 128, 256, EDGE_SMEM>>>(eidx, ea, out, E, N);
}

// round 6
// speedup vs baseline: 1.6240x; 1.1962x over previous
#include <cuda_runtime.h>
#include <cstdint>

#define MAX_NODES 50000
__device__ float    g_xw[(size_t)MAX_NODES * 128];   // x @ W[64:192] + b (fp32)
__device__ uint2    g_wt2[8 * 128 * 4];              // W[0:64] tf32, packed frags

typedef unsigned long long u64;

// ---------------- helpers ----------------
__device__ __forceinline__ void ffma2(u64& acc, u64 a, u64 w) {
    asm("fma.rn.f32x2 %0, %1, %2, %0;" : "+l"(acc) : "l"(a), "l"(w));
}
__device__ __forceinline__ u64 dup2(float v) {
    u64 d; asm("mov.b64 %0, {%1, %1};" : "=l"(d) : "f"(v)); return d;
}
__device__ __forceinline__ float2 unpk(u64 d) {
    float2 r; asm("mov.b64 {%0, %1}, %2;" : "=f"(r.x), "=f"(r.y) : "l"(d)); return r;
}
__device__ __forceinline__ void red_add_v4(float* p, float a, float b, float c, float d) {
    asm volatile("red.global.add.v4.f32 [%0], {%1,%2,%3,%4};"
                 :: "l"(p), "f"(a), "f"(b), "f"(c), "f"(d) : "memory");
}
__device__ __forceinline__ uint32_t tf32r(float f) {
    uint32_t r; asm("cvt.rna.tf32.f32 %0, %1;" : "=r"(r) : "f"(f)); return r;
}
__device__ __forceinline__ uint32_t smem_u32(const void* p) {
    uint32_t a;
    asm("{ .reg .u64 t; cvta.to.shared.u64 t, %1; cvt.u32.u64 %0, t; }" : "=r"(a) : "l"(p));
    return a;
}
__device__ __forceinline__ void cp_async16(uint32_t dst, const void* src) {
    asm volatile("cp.async.cg.shared.global [%0], [%1], 16;" :: "r"(dst), "l"(src));
}
__device__ __forceinline__ void mma_tf32(float& c0, float& c1, float& c2, float& c3,
                                         uint32_t a0, uint32_t a1, uint32_t a2, uint32_t a3,
                                         uint32_t b0, uint32_t b1) {
    asm volatile("mma.sync.aligned.m16n8k8.row.col.f32.tf32.tf32.f32 "
                 "{%0,%1,%2,%3}, {%4,%5,%6,%7}, {%8,%9}, {%0,%1,%2,%3};"
                 : "+f"(c0), "+f"(c1), "+f"(c2), "+f"(c3)
                 : "r"(a0), "r"(a1), "r"(a2), "r"(a3), "r"(b0), "r"(b1));
}

// ---------------------------------------------------------------------------
// Kernel 0: prep W[0:64] into mma B-fragment layout, tf32, column-permuted.
// ---------------------------------------------------------------------------
__global__ void wt_prep_kernel(const float* __restrict__ W) {
    int i = blockIdx.x * 256 + threadIdx.x;   // 4096 entries
    if (i >= 4096) return;
    int kstep = i >> 9;
    int n     = (i >> 2) & 127;
    int c     = i & 3;
    int q = n & 15;
    int l;
    if (q < 8) l = (n & ~15) + 4 * (q >> 1) + (q & 1);
    else       l = (n & ~15) + 4 * ((q - 8) >> 1) + 2 + (q & 1);
    int k0 = kstep * 8 + c;
    g_wt2[i] = make_uint2(tf32r(W[(size_t)k0 * 128 + l]),
                          tf32r(W[(size_t)(k0 + 4) * 128 + l]));
}

// ---------------------------------------------------------------------------
// Kernel 1: node precompute  xW = x @ W[64:192] + b  (fp32, f32x2 FMA)
// ---------------------------------------------------------------------------
__global__ __launch_bounds__(256, 2)
void node_xw_kernel(const float* __restrict__ x,
                    const float* __restrict__ W,   // [192][128]
                    const float* __restrict__ b,
                    int N) {
    extern __shared__ float sm[];
    float* W_s = sm;                       // 8192 floats
    u64*   x2  = (u64*)(sm + 8192);        // 8192 u64

    const int tid = threadIdx.x;
    const int tx = tid & 15, ty = tid >> 4;
    const int n0 = blockIdx.x * 128;

    u64 acc[8][4];
#pragma unroll
    for (int i = 0; i < 8; i++)
#pragma unroll
        for (int j = 0; j < 4; j++) acc[i][j] = 0ull;

    for (int kc = 0; kc < 2; kc++) {
        __syncthreads();
#pragma unroll
        for (int it = 0; it < 8; it++) {
            int i = tid + it * 256;
            int k = i >> 5, oq = i & 31;
            *(float4*)&W_s[k * 128 + oq * 4] =
                *(const float4*)&W[(size_t)(64 + kc * 64 + k) * 128 + oq * 4];
        }
#pragma unroll
        for (int it = 0; it < 8; it++) {
            int i = tid + it * 256;
            int n = i >> 4, kq = i & 15;
            float4 v = make_float4(0.f, 0.f, 0.f, 0.f);
            if (n0 + n < N)
                v = *(const float4*)&x[(size_t)(n0 + n) * 128 + kc * 64 + kq * 4];
            int cs = (((n >> 1) ^ kq) << 1) + (n & 1);
            u64* row = x2 + (kq * 4) * 128 + cs;
            row[0]   = dup2(v.x);
            row[128] = dup2(v.y);
            row[256] = dup2(v.z);
            row[384] = dup2(v.w);
        }
        __syncthreads();

#pragma unroll 4
        for (int k = 0; k < 64; k++) {
            int kq = k >> 2;
            const u64* base = x2 + k * 128;
            ulonglong2 aA0 = *(const ulonglong2*)(base + ((( 2*ty    ) ^ kq) << 1));
            ulonglong2 aA1 = *(const ulonglong2*)(base + ((( 2*ty + 1) ^ kq) << 1));
            ulonglong2 aB0 = *(const ulonglong2*)(base + (((32 + 2*ty) ^ kq) << 1));
            ulonglong2 aB1 = *(const ulonglong2*)(base + (((33 + 2*ty) ^ kq) << 1));
            ulonglong2 w0 = *(const ulonglong2*)&W_s[k * 128 + tx * 4];
            ulonglong2 w1 = *(const ulonglong2*)&W_s[k * 128 + 64 + tx * 4];
            u64 a2[8] = {aA0.x, aA0.y, aA1.x, aA1.y, aB0.x, aB0.y, aB1.x, aB1.y};
#pragma unroll
            for (int i = 0; i < 8; i++) {
                ffma2(acc[i][0], a2[i], w0.x);
                ffma2(acc[i][1], a2[i], w0.y);
                ffma2(acc[i][2], a2[i], w1.x);
                ffma2(acc[i][3], a2[i], w1.y);
            }
        }
    }

    float4 b0 = *(const float4*)&b[tx * 4];
    float4 b1 = *(const float4*)&b[64 + tx * 4];
#pragma unroll
    for (int i = 0; i < 8; i++) {
        int n = (i < 4) ? (ty * 4 + i) : (64 + ty * 4 + (i - 4));
        if (n0 + n >= N) continue;
        float2 p0 = unpk(acc[i][0]), p1 = unpk(acc[i][1]);
        float2 p2 = unpk(acc[i][2]), p3 = unpk(acc[i][3]);
        float* p = &g_xw[(size_t)(n0 + n) * 128];
        *(float4*)&p[tx * 4] =
            make_float4(p0.x + b0.x, p0.y + b0.y, p1.x + b0.z, p1.y + b0.w);
        *(float4*)&p[64 + tx * 4] =
            make_float4(p2.x + b1.x, p2.y + b1.y, p3.x + b1.z, p3.y + b1.w);
    }
}

// ---------------------------------------------------------------------------
// Kernel 2: persistent edge GEMM, cp.async double-buffered A + idx, B once.
// A buffers: [128 edges][64 floats], 16B-chunk XOR swizzle (q ^ (e&7)).
// smem map: A0 @0 (32KB), A1 @32768, B @65536 (32KB), idx @98304 (2x1KB)
// ---------------------------------------------------------------------------
#define A_BUF   32768
#define B_OFF   65536
#define IDX_OFF 98304
#define EDGE_SMEM (IDX_OFF + 2048)   // 100352

__global__ __launch_bounds__(256, 2)
void edge_mma_kernel(const int* __restrict__ eidx,   // [2][E] int32
                     const float* __restrict__ ea,   // [E][64]
                     float* __restrict__ out,        // [N][128]
                     int E, int N, int ntiles) {
    extern __shared__ char smem[];
    const uint32_t sb = smem_u32(smem);
    uint2* B_s = (uint2*)(smem + B_OFF);

    const int tid  = threadIdx.x;
    const int wid  = tid >> 5, lane = tid & 31;
    const int g    = lane >> 2, t = lane & 3;
    const int wbase = wid * 16;

    // B once per CTA (32 KB, L2-resident after first wave)
    {
        const uint4* srcp = (const uint4*)g_wt2;
        uint4* dstp = (uint4*)B_s;
#pragma unroll
        for (int it = 0; it < 8; it++)
            dstp[tid + it * 256] = srcp[tid + it * 256];
    }

    // ---- async tile issue: A (swizzled) + indices ----
    auto issue_tile = [&](int tile, int p) {
        size_t ebase = (size_t)tile * 128;
#pragma unroll
        for (int it = 0; it < 8; it++) {
            int i = tid + it * 256;           // 2048 16B chunks
            int e = i >> 4, q = i & 15;
            size_t se = ebase + e;
            if (se > (size_t)E - 1) se = (size_t)E - 1;   // clamp (safety)
            uint32_t dst = sb + p * A_BUF + e * 256 + ((q ^ (e & 7)) << 4);
            cp_async16(dst, ea + se * 64 + q * 4);
        }
        if (tid < 32) {
            cp_async16(sb + IDX_OFF + p * 1024 + tid * 16, eidx + ebase + tid * 4);
        } else if (tid < 64) {
            cp_async16(sb + IDX_OFF + p * 1024 + 512 + (tid - 32) * 16,
                       eidx + (size_t)E + ebase + (tid - 32) * 4);
        }
        asm volatile("cp.async.commit_group;" ::: "memory");
    };

    int tile = blockIdx.x;
    if (tile < ntiles) issue_tile(tile, 0);
    int p = 0;

    for (; tile < ntiles; tile += gridDim.x) {
        int next = tile + gridDim.x;
        if (next < ntiles) {
            issue_tile(next, p ^ 1);
            asm volatile("cp.async.wait_group 1;" ::: "memory");
        } else {
            asm volatile("cp.async.wait_group 0;" ::: "memory");
        }
        __syncthreads();

        const float* Abuf = (const float*)(smem + p * A_BUF);
        const int* src_s = (const int*)(smem + IDX_OFF + p * 1024);
        const int* dst_s = src_s + 128;

        float acc[16][4];
#pragma unroll
        for (int nt = 0; nt < 16; nt++)
#pragma unroll
            for (int j = 0; j < 4; j++) acc[nt][j] = 0.0f;

        const float* ar0 = Abuf + (wbase + g) * 64;
        const float* ar1 = Abuf + (wbase + 8 + g) * 64;
#pragma unroll
        for (int ks = 0; ks < 8; ks++) {
            int c0 = (((2 * ks)     ^ g) << 2) + t;
            int c1 = (((2 * ks + 1) ^ g) << 2) + t;
            uint32_t a0 = tf32r(ar0[c0]);
            uint32_t a1 = tf32r(ar1[c0]);
            uint32_t a2 = tf32r(ar0[c1]);
            uint32_t a3 = tf32r(ar1[c1]);
            const uint2* brow = B_s + ks * 512 + g * 4 + t;
#pragma unroll
            for (int nt = 0; nt < 16; nt++) {
                uint2 bv = brow[nt * 32];
                mma_tf32(acc[nt][0], acc[nt][1], acc[nt][2], acc[nt][3],
                         a0, a1, a2, a3, bv.x, bv.y);
            }
        }

        // epilogue: gather xW[src], ReLU, vector atomic scatter
        size_t ebase = (size_t)tile * 128;
#pragma unroll
        for (int rs = 0; rs < 2; rs++) {
            int m = wbase + g + 8 * rs;
            int s = src_s[m];
            int d = dst_s[m];
            if (ebase + m >= (size_t)E ||
                (unsigned)s >= (unsigned)N || (unsigned)d >= (unsigned)N)
                continue;
            const float* gp = &g_xw[(size_t)s * 128];
            float* op = &out[(size_t)d * 128];
#pragma unroll
            for (int q = 0; q < 8; q++) {
                int lc = q * 16 + 4 * t;
                float4 gv = *(const float4*)&gp[lc];
                float v0 = fmaxf(acc[2 * q    ][rs * 2    ] + gv.x, 0.f);
                float v1 = fmaxf(acc[2 * q    ][rs * 2 + 1] + gv.y, 0.f);
                float v2 = fmaxf(acc[2 * q + 1][rs * 2    ] + gv.z, 0.f);
                float v3 = fmaxf(acc[2 * q + 1][rs * 2 + 1] + gv.w, 0.f);
                red_add_v4(op + lc, v0, v1, v2, v3);
            }
        }
        __syncthreads();   // buffer p may be re-filled next iteration
        p ^= 1;
    }
}

extern "C" void kernel_launch(void* const* d_in, const int* in_sizes, int n_in,
                              void* d_out, int out_size) {
    const float* x    = (const float*)d_in[0];
    const int*   eidx = (const int*)d_in[1];   // int32 [2][E]
    const float* ea   = (const float*)d_in[2];
    const float* W    = (const float*)d_in[3];
    const float* b    = (const float*)d_in[4];
    float* out = (float*)d_out;

    const int N = in_sizes[0] / 128;   // 50000
    const int E = in_sizes[2] / 64;    // 800000
    const int ntiles = (E + 127) / 128;

    const int node_smem = 8192 * 4 + 8192 * 8;   // 96 KB

    cudaFuncSetAttribute(node_xw_kernel,
                         cudaFuncAttributeMaxDynamicSharedMemorySize, node_smem);
    cudaFuncSetAttribute(edge_mma_kernel,
                         cudaFuncAttributeMaxDynamicSharedMemorySize, EDGE_SMEM);

    cudaMemsetAsync(d_out, 0, (size_t)out_size * sizeof(float), 0);

    wt_prep_kernel<<<16, 256>>>(W);
    node_xw_kernel<<<(N + 127) / 128, 256, node_smem>>>(x, W, b, N);

    int grid = ntiles < 296 ? ntiles : 296;
    edge_mma_kernel<<<grid, 256, EDGE_SMEM>>>(eidx, ea, out, E, N, ntiles);
}

// round 7
// speedup vs baseline: 1.8550x; 1.1423x over previous
#include <cuda_runtime.h>
#include <cstdint>

#define MAX_NODES 50000
__device__ float g_xw[(size_t)MAX_NODES * 128];   // x @ W[64:192] + b (fp32)

typedef unsigned long long u64;

// ---------------- helpers ----------------
__device__ __forceinline__ void red_add_v4(float* p, float a, float b, float c, float d) {
    asm volatile("red.global.add.v4.f32 [%0], {%1,%2,%3,%4};"
                 :: "l"(p), "f"(a), "f"(b), "f"(c), "f"(d) : "memory");
}
__device__ __forceinline__ uint32_t tf32r(float f) {
    uint32_t r; asm("cvt.rna.tf32.f32 %0, %1;" : "=r"(r) : "f"(f)); return r;
}
__device__ __forceinline__ uint32_t smem_u32(const void* p) {
    uint32_t a;
    asm("{ .reg .u64 t; cvta.to.shared.u64 t, %1; cvt.u32.u64 %0, t; }" : "=r"(a) : "l"(p));
    return a;
}
__device__ __forceinline__ void cp_async16(uint32_t dst, const void* src) {
    asm volatile("cp.async.cg.shared.global [%0], [%1], 16;" :: "r"(dst), "l"(src));
}
__device__ __forceinline__ void mma_tf32(float& c0, float& c1, float& c2, float& c3,
                                         uint32_t a0, uint32_t a1, uint32_t a2, uint32_t a3,
                                         uint32_t b0, uint32_t b1) {
    asm volatile("mma.sync.aligned.m16n8k8.row.col.f32.tf32.tf32.f32 "
                 "{%0,%1,%2,%3}, {%4,%5,%6,%7}, {%8,%9}, {%0,%1,%2,%3};"
                 : "+f"(c0), "+f"(c1), "+f"(c2), "+f"(c3)
                 : "r"(a0), "r"(a1), "r"(a2), "r"(a3), "r"(b0), "r"(b1));
}
// logical column for physical fragment column n (so each thread's 4 cols are contiguous)
__device__ __forceinline__ int colperm(int n) {
    int q = n & 15;
    return (q < 8) ? (n & ~15) + 4 * (q >> 1) + (q & 1)
                   : (n & ~15) + 4 * ((q - 8) >> 1) + 2 + (q & 1);
}

// ---------------------------------------------------------------------------
// Kernel A (fused): blocks [0,NB_ZERO) zero `out`; the rest run the node GEMM
// xW = x @ W[64:192] + b on mma.sync tf32 (K=128 = 2 phases of 64).
// node smem: B_s 64KB @0 | A 32KB @65536 | bias 512B @98304
// ---------------------------------------------------------------------------
#define NB_ZERO  128
#define NA_OFF   65536
#define NBIAS_OFF 98304
#define NODE_SMEM (NBIAS_OFF + 512)

__global__ __launch_bounds__(256, 2)
void node_fused_kernel(const float* __restrict__ x,
                       const float* __restrict__ W,   // [192][128]
                       const float* __restrict__ b,
                       float* __restrict__ out, int out_n,
                       int N, int ntiles) {
    const int tid = threadIdx.x;

    if (blockIdx.x < NB_ZERO) {               // zero the output buffer
        float4 z = make_float4(0.f, 0.f, 0.f, 0.f);
        int total4 = out_n >> 2;
        for (int i = blockIdx.x * 256 + tid; i < total4; i += NB_ZERO * 256)
            ((float4*)out)[i] = z;
        return;
    }

    extern __shared__ char smem[];
    const uint32_t sb = smem_u32(smem);
    uint2* B_s   = (uint2*)smem;
    float* bias_s = (float*)(smem + NBIAS_OFF);

    const int wid  = tid >> 5, lane = tid & 31;
    const int g    = lane >> 2, t = lane & 3;
    const int wbase = wid * 16;
    const int tile = blockIdx.x - NB_ZERO;
    if (tile >= ntiles) return;
    const int n0 = tile * 128;

    // build B fragments from W rows [64,192): 8192 uint2 entries
#pragma unroll
    for (int it = 0; it < 32; it++) {
        int i = tid + it * 256;
        int c = i & 3, n = (i >> 2) & 127, ks = i >> 9;
        int l = colperm(n);
        int k0 = 64 + ks * 8 + c;
        B_s[i] = make_uint2(tf32r(W[(size_t)k0 * 128 + l]),
                            tf32r(W[(size_t)(k0 + 4) * 128 + l]));
    }
    if (tid < 128) bias_s[tid] = b[tid];

    float acc[16][4];
#pragma unroll
    for (int nt = 0; nt < 16; nt++)
#pragma unroll
        for (int j = 0; j < 4; j++) acc[nt][j] = 0.0f;

    for (int h = 0; h < 2; h++) {
        // fill A with x[n0..n0+128)[h*64 .. h*64+64), 16B-chunk XOR swizzle
#pragma unroll
        for (int it = 0; it < 8; it++) {
            int i = tid + it * 256;
            int e = i >> 4, q = i & 15;
            int n = n0 + e; if (n > N - 1) n = N - 1;
            uint32_t dst = sb + NA_OFF + e * 256 + ((q ^ (e & 7)) << 4);
            cp_async16(dst, x + (size_t)n * 128 + h * 64 + q * 4);
        }
        asm volatile("cp.async.commit_group;" ::: "memory");
        asm volatile("cp.async.wait_group 0;" ::: "memory");
        __syncthreads();

        const float* Abuf = (const float*)(smem + NA_OFF);
        const float* ar0 = Abuf + (wbase + g) * 64;
        const float* ar1 = Abuf + (wbase + 8 + g) * 64;
#pragma unroll
        for (int ks = 0; ks < 8; ks++) {
            int c0 = (((2 * ks)     ^ g) << 2) + t;
            int c1 = (((2 * ks + 1) ^ g) << 2) + t;
            uint32_t a0 = tf32r(ar0[c0]);
            uint32_t a1 = tf32r(ar1[c0]);
            uint32_t a2 = tf32r(ar0[c1]);
            uint32_t a3 = tf32r(ar1[c1]);
            const uint2* brow = B_s + (h * 8 + ks) * 512 + g * 4 + t;
#pragma unroll
            for (int nt = 0; nt < 16; nt++) {
                uint2 bv = brow[nt * 32];
                mma_tf32(acc[nt][0], acc[nt][1], acc[nt][2], acc[nt][3],
                         a0, a1, a2, a3, bv.x, bv.y);
            }
        }
        if (h == 0) __syncthreads();   // A buffer reused for half 1
    }

    // epilogue: add bias, store fp32 rows of g_xw
#pragma unroll
    for (int rs = 0; rs < 2; rs++) {
        int m = wbase + g + 8 * rs;
        int n = n0 + m;
        if (n >= N) continue;
        float* p = &g_xw[(size_t)n * 128];
#pragma unroll
        for (int q = 0; q < 8; q++) {
            int lc = q * 16 + 4 * t;
            float4 bv = *(const float4*)&bias_s[lc];
            float4 v = make_float4(acc[2 * q    ][rs * 2    ] + bv.x,
                                   acc[2 * q    ][rs * 2 + 1] + bv.y,
                                   acc[2 * q + 1][rs * 2    ] + bv.z,
                                   acc[2 * q + 1][rs * 2 + 1] + bv.w);
            *(float4*)&p[lc] = v;
        }
    }
}

// ---------------------------------------------------------------------------
// Kernel B: persistent edge GEMM, cp.async double-buffered A + idx.
// B fragments built in smem from W[0:64] at CTA start.
// smem: A0 @0 (32KB), A1 @32768, B @65536 (32KB), idx @98304 (2x1KB)
// ---------------------------------------------------------------------------
#define A_BUF   32768
#define B_OFF   65536
#define IDX_OFF 98304
#define EDGE_SMEM (IDX_OFF + 2048)   // 100352

__global__ __launch_bounds__(256, 2)
void edge_mma_kernel(const int* __restrict__ eidx,   // [2][E] int32
                     const float* __restrict__ ea,   // [E][64]
                     const float* __restrict__ W,    // [192][128]
                     float* __restrict__ out,        // [N][128]
                     int E, int N, int ntiles) {
    extern __shared__ char smem[];
    const uint32_t sb = smem_u32(smem);
    uint2* B_s = (uint2*)(smem + B_OFF);

    const int tid  = threadIdx.x;
    const int wid  = tid >> 5, lane = tid & 31;
    const int g    = lane >> 2, t = lane & 3;
    const int wbase = wid * 16;

    // build B fragments from W rows [0,64): 4096 uint2 entries
#pragma unroll
    for (int it = 0; it < 16; it++) {
        int i = tid + it * 256;
        int c = i & 3, n = (i >> 2) & 127, ks = i >> 9;
        int l = colperm(n);
        int k0 = ks * 8 + c;
        B_s[i] = make_uint2(tf32r(W[(size_t)k0 * 128 + l]),
                            tf32r(W[(size_t)(k0 + 4) * 128 + l]));
    }

    // ---- async tile issue: A (swizzled) + indices ----
    auto issue_tile = [&](int tile, int p) {
        size_t ebase = (size_t)tile * 128;
#pragma unroll
        for (int it = 0; it < 8; it++) {
            int i = tid + it * 256;           // 2048 16B chunks
            int e = i >> 4, q = i & 15;
            size_t se = ebase + e;
            if (se > (size_t)E - 1) se = (size_t)E - 1;
            uint32_t dst = sb + p * A_BUF + e * 256 + ((q ^ (e & 7)) << 4);
            cp_async16(dst, ea + se * 64 + q * 4);
        }
        if (tid < 32) {
            cp_async16(sb + IDX_OFF + p * 1024 + tid * 16, eidx + ebase + tid * 4);
        } else if (tid < 64) {
            cp_async16(sb + IDX_OFF + p * 1024 + 512 + (tid - 32) * 16,
                       eidx + (size_t)E + ebase + (tid - 32) * 4);
        }
        asm volatile("cp.async.commit_group;" ::: "memory");
    };

    int tile = blockIdx.x;
    if (tile < ntiles) issue_tile(tile, 0);
    int p = 0;

    for (; tile < ntiles; tile += gridDim.x) {
        int next = tile + gridDim.x;
        if (next < ntiles) {
            issue_tile(next, p ^ 1);
            asm volatile("cp.async.wait_group 1;" ::: "memory");
        } else {
            asm volatile("cp.async.wait_group 0;" ::: "memory");
        }
        __syncthreads();

        const float* Abuf = (const float*)(smem + p * A_BUF);
        const int* src_s = (const int*)(smem + IDX_OFF + p * 1024);
        const int* dst_s = src_s + 128;

        float acc[16][4];
#pragma unroll
        for (int nt = 0; nt < 16; nt++)
#pragma unroll
            for (int j = 0; j < 4; j++) acc[nt][j] = 0.0f;

        const float* ar0 = Abuf + (wbase + g) * 64;
        const float* ar1 = Abuf + (wbase + 8 + g) * 64;
#pragma unroll
        for (int ks = 0; ks < 8; ks++) {
            int c0 = (((2 * ks)     ^ g) << 2) + t;
            int c1 = (((2 * ks + 1) ^ g) << 2) + t;
            uint32_t a0 = tf32r(ar0[c0]);
            uint32_t a1 = tf32r(ar1[c0]);
            uint32_t a2 = tf32r(ar0[c1]);
            uint32_t a3 = tf32r(ar1[c1]);
            const uint2* brow = B_s + ks * 512 + g * 4 + t;
#pragma unroll
            for (int nt = 0; nt < 16; nt++) {
                uint2 bv = brow[nt * 32];
                mma_tf32(acc[nt][0], acc[nt][1], acc[nt][2], acc[nt][3],
                         a0, a1, a2, a3, bv.x, bv.y);
            }
        }

        // epilogue: gather xW[src], ReLU, vector atomic scatter
        size_t ebase = (size_t)tile * 128;
#pragma unroll
        for (int rs = 0; rs < 2; rs++) {
            int m = wbase + g + 8 * rs;
            int s = src_s[m];
            int d = dst_s[m];
            if (ebase + m >= (size_t)E ||
                (unsigned)s >= (unsigned)N || (unsigned)d >= (unsigned)N)
                continue;
            const float* gp = &g_xw[(size_t)s * 128];
            float* op = &out[(size_t)d * 128];
#pragma unroll
            for (int q = 0; q < 8; q++) {
                int lc = q * 16 + 4 * t;
                float4 gv = *(const float4*)&gp[lc];
                float v0 = fmaxf(acc[2 * q    ][rs * 2    ] + gv.x, 0.f);
                float v1 = fmaxf(acc[2 * q    ][rs * 2 + 1] + gv.y, 0.f);
                float v2 = fmaxf(acc[2 * q + 1][rs * 2    ] + gv.z, 0.f);
                float v3 = fmaxf(acc[2 * q + 1][rs * 2 + 1] + gv.w, 0.f);
                red_add_v4(op + lc, v0, v1, v2, v3);
            }
        }
        __syncthreads();   // buffer p may be re-filled next iteration
        p ^= 1;
    }
}

extern "C" void kernel_launch(void* const* d_in, const int* in_sizes, int n_in,
                              void* d_out, int out_size) {
    const float* x    = (const float*)d_in[0];
    const int*   eidx = (const int*)d_in[1];   // int32 [2][E]
    const float* ea   = (const float*)d_in[2];
    const float* W    = (const float*)d_in[3];
    const float* b    = (const float*)d_in[4];
    float* out = (float*)d_out;

    const int N = in_sizes[0] / 128;   // 50000
    const int E = in_sizes[2] / 64;    // 800000
    const int ntilesN = (N + 127) / 128;
    const int ntilesE = (E + 127) / 128;

    cudaFuncSetAttribute(node_fused_kernel,
                         cudaFuncAttributeMaxDynamicSharedMemorySize, NODE_SMEM);
    cudaFuncSetAttribute(edge_mma_kernel,
                         cudaFuncAttributeMaxDynamicSharedMemorySize, EDGE_SMEM);

    node_fused_kernel<<<NB_ZERO + ntilesN, 256, NODE_SMEM>>>(x, W, b, out, out_size, N, ntilesN);

    int grid = ntilesE < 296 ? ntilesE : 296;
    edge_mma_kernel<<<grid, 256, EDGE_SMEM>>>(eidx, ea, W, out, E, N, ntilesE);
}

// round 8
// speedup vs baseline: 2.0702x; 1.1160x over previous
#include <cuda_runtime.h>
#include <cstdint>

#define MAX_NODES 50000
__device__ float g_xw[(size_t)MAX_NODES * 128];   // x @ W[64:192] + b (fp32)

// ---------------- helpers ----------------
__device__ __forceinline__ void red_add_v4(float* p, float a, float b, float c, float d) {
    asm volatile("red.global.add.v4.f32 [%0], {%1,%2,%3,%4};"
                 :: "l"(p), "f"(a), "f"(b), "f"(c), "f"(d) : "memory");
}
__device__ __forceinline__ uint32_t tf32r(float f) {
    uint32_t r; asm("cvt.rna.tf32.f32 %0, %1;" : "=r"(r) : "f"(f)); return r;
}
__device__ __forceinline__ uint32_t smem_u32(const void* p) {
    uint32_t a;
    asm("{ .reg .u64 t; cvta.to.shared.u64 t, %1; cvt.u32.u64 %0, t; }" : "=r"(a) : "l"(p));
    return a;
}
__device__ __forceinline__ void cp_async16(uint32_t dst, const void* src) {
    asm volatile("cp.async.cg.shared.global [%0], [%1], 16;" :: "r"(dst), "l"(src));
}
__device__ __forceinline__ void mma_tf32(float& c0, float& c1, float& c2, float& c3,
                                         uint32_t a0, uint32_t a1, uint32_t a2, uint32_t a3,
                                         uint32_t b0, uint32_t b1) {
    asm volatile("mma.sync.aligned.m16n8k8.row.col.f32.tf32.tf32.f32 "
                 "{%0,%1,%2,%3}, {%4,%5,%6,%7}, {%8,%9}, {%0,%1,%2,%3};"
                 : "+f"(c0), "+f"(c1), "+f"(c2), "+f"(c3)
                 : "r"(a0), "r"(a1), "r"(a2), "r"(a3), "r"(b0), "r"(b1));
}
// logical column for physical fragment column n (each thread's 4 cols contiguous)
__device__ __forceinline__ int colperm(int n) {
    int q = n & 15;
    return (q < 8) ? (n & ~15) + 4 * (q >> 1) + (q & 1)
                   : (n & ~15) + 4 * ((q - 8) >> 1) + 2 + (q & 1);
}

// ---------------------------------------------------------------------------
// Kernel A (fused): blocks [0,NB_ZERO) zero `out`; the rest run the node GEMM
// xW = x @ W[64:192] + b on mma.sync tf32 (K=128 = 2 phases of 64).
// node smem: B_s 64KB @0 | A 32KB @65536 | bias 512B @98304
// ---------------------------------------------------------------------------
#define NB_ZERO  128
#define NA_OFF   65536
#define NBIAS_OFF 98304
#define NODE_SMEM (NBIAS_OFF + 512)

__global__ __launch_bounds__(256, 2)
void node_fused_kernel(const float* __restrict__ x,
                       const float* __restrict__ W,   // [192][128]
                       const float* __restrict__ b,
                       float* __restrict__ out, int out_n,
                       int N, int ntiles) {
    const int tid = threadIdx.x;

    if (blockIdx.x < NB_ZERO) {               // zero the output buffer
        float4 z = make_float4(0.f, 0.f, 0.f, 0.f);
        int total4 = out_n >> 2;
        for (int i = blockIdx.x * 256 + tid; i < total4; i += NB_ZERO * 256)
            ((float4*)out)[i] = z;
        return;
    }

    extern __shared__ char smem[];
    const uint32_t sb = smem_u32(smem);
    uint2* B_s   = (uint2*)smem;
    float* bias_s = (float*)(smem + NBIAS_OFF);

    const int wid  = tid >> 5, lane = tid & 31;
    const int g    = lane >> 2, t = lane & 3;
    const int wbase = wid * 16;
    const int tile = blockIdx.x - NB_ZERO;
    if (tile >= ntiles) return;
    const int n0 = tile * 128;

    // build B fragments from W rows [64,192): 8192 uint2 entries
#pragma unroll
    for (int it = 0; it < 32; it++) {
        int i = tid + it * 256;
        int c = i & 3, n = (i >> 2) & 127, ks = i >> 9;
        int l = colperm(n);
        int k0 = 64 + ks * 8 + c;
        B_s[i] = make_uint2(tf32r(W[(size_t)k0 * 128 + l]),
                            tf32r(W[(size_t)(k0 + 4) * 128 + l]));
    }
    if (tid < 128) bias_s[tid] = b[tid];

    float acc[16][4];
#pragma unroll
    for (int nt = 0; nt < 16; nt++)
#pragma unroll
        for (int j = 0; j < 4; j++) acc[nt][j] = 0.0f;

    for (int h = 0; h < 2; h++) {
#pragma unroll
        for (int it = 0; it < 8; it++) {
            int i = tid + it * 256;
            int e = i >> 4, q = i & 15;
            int n = n0 + e; if (n > N - 1) n = N - 1;
            uint32_t dst = sb + NA_OFF + e * 256 + ((q ^ (e & 7)) << 4);
            cp_async16(dst, x + (size_t)n * 128 + h * 64 + q * 4);
        }
        asm volatile("cp.async.commit_group;" ::: "memory");
        asm volatile("cp.async.wait_group 0;" ::: "memory");
        __syncthreads();

        const float* Abuf = (const float*)(smem + NA_OFF);
        const float* ar0 = Abuf + (wbase + g) * 64;
        const float* ar1 = Abuf + (wbase + 8 + g) * 64;
#pragma unroll
        for (int ks = 0; ks < 8; ks++) {
            int c0 = (((2 * ks)     ^ g) << 2) + t;
            int c1 = (((2 * ks + 1) ^ g) << 2) + t;
            uint32_t a0 = tf32r(ar0[c0]);
            uint32_t a1 = tf32r(ar1[c0]);
            uint32_t a2 = tf32r(ar0[c1]);
            uint32_t a3 = tf32r(ar1[c1]);
            const uint2* brow = B_s + (h * 8 + ks) * 512 + g * 4 + t;
#pragma unroll
            for (int nt = 0; nt < 16; nt++) {
                uint2 bv = brow[nt * 32];
                mma_tf32(acc[nt][0], acc[nt][1], acc[nt][2], acc[nt][3],
                         a0, a1, a2, a3, bv.x, bv.y);
            }
        }
        if (h == 0) __syncthreads();   // A buffer reused for half 1
    }

    // epilogue: add bias, store fp32 rows of g_xw
#pragma unroll
    for (int rs = 0; rs < 2; rs++) {
        int m = wbase + g + 8 * rs;
        int n = n0 + m;
        if (n >= N) continue;
        float* p = &g_xw[(size_t)n * 128];
#pragma unroll
        for (int q = 0; q < 8; q++) {
            int lc = q * 16 + 4 * t;
            float4 bv = *(const float4*)&bias_s[lc];
            float4 v = make_float4(acc[2 * q    ][rs * 2    ] + bv.x,
                                   acc[2 * q    ][rs * 2 + 1] + bv.y,
                                   acc[2 * q + 1][rs * 2    ] + bv.z,
                                   acc[2 * q + 1][rs * 2 + 1] + bv.w);
            *(float4*)&p[lc] = v;
        }
    }
}

// ---------------------------------------------------------------------------
// Kernel B: warp-autonomous edge pipeline. Each warp streams independent
// 16-edge tiles with its own double-buffered cp.async slices; no block syncs
// in the mainloop. B fragments (32KB) built once per CTA.
// smem: B @0 (32KB) | warp w: A bufs 2x4KB @ 32768 + w*8192
// ---------------------------------------------------------------------------
#define B_OFF   0
#define AW_OFF  32768
#define EDGE_SMEM (AW_OFF + 8 * 8192)   // 98304

__global__ __launch_bounds__(256, 2)
void edge_mma_kernel(const int* __restrict__ eidx,   // [2][E] int32
                     const float* __restrict__ ea,   // [E][64]
                     const float* __restrict__ W,    // [192][128]
                     float* __restrict__ out,        // [N][128]
                     int E, int N, int nwtiles) {
    extern __shared__ char smem[];
    const uint32_t sb = smem_u32(smem);
    uint2* B_s = (uint2*)(smem + B_OFF);

    const int tid  = threadIdx.x;
    const int wid  = tid >> 5, lane = tid & 31;
    const int g    = lane >> 2, t = lane & 3;

    // build B fragments from W rows [0,64): 4096 uint2 entries
#pragma unroll
    for (int it = 0; it < 16; it++) {
        int i = tid + it * 256;
        int c = i & 3, n = (i >> 2) & 127, ks = i >> 9;
        int l = colperm(n);
        int k0 = ks * 8 + c;
        B_s[i] = make_uint2(tf32r(W[(size_t)k0 * 128 + l]),
                            tf32r(W[(size_t)(k0 + 4) * 128 + l]));
    }
    __syncthreads();

    const uint32_t a_base = sb + AW_OFF + wid * 8192;
    const float*   a_ptr0 = (const float*)(smem + AW_OFF + wid * 8192);

    // per-warp async A-slice issue (16 edges x 64 floats, chunk-XOR swizzle)
    auto issue = [&](int wt, int p) {
        size_t ebase = (size_t)wt * 16;
#pragma unroll
        for (int it = 0; it < 8; it++) {
            int i = lane + it * 32;          // 256 16B chunks
            int e = i >> 4, q = i & 15;
            size_t se = ebase + e;
            if (se > (size_t)E - 1) se = (size_t)E - 1;
            cp_async16(a_base + p * 4096 + e * 256 + ((q ^ (e & 7)) << 4),
                       ea + se * 64 + q * 4);
        }
        asm volatile("cp.async.commit_group;" ::: "memory");
    };

    const int stride = gridDim.x * 8;
    int wt = blockIdx.x * 8 + wid;
    if (wt < nwtiles) issue(wt, 0);
    int p = 0;

    for (; wt < nwtiles; wt += stride) {
        int next = wt + stride;
        __syncwarp();                       // all lanes done with buffer p^1
        if (next < nwtiles) {
            issue(next, p ^ 1);
            asm volatile("cp.async.wait_group 1;" ::: "memory");
        } else {
            asm volatile("cp.async.wait_group 0;" ::: "memory");
        }
        __syncwarp();

        size_t ebase = (size_t)wt * 16;
        // prefetch indices (latency hides under the MMA loop)
        int m0 = g, m1 = g + 8;
        bool v0e = ebase + m0 < (size_t)E;
        bool v1e = ebase + m1 < (size_t)E;
        int s0 = v0e ? eidx[ebase + m0] : -1;
        int d0 = v0e ? eidx[(size_t)E + ebase + m0] : -1;
        int s1 = v1e ? eidx[ebase + m1] : -1;
        int d1 = v1e ? eidx[(size_t)E + ebase + m1] : -1;

        float acc[16][4];
#pragma unroll
        for (int nt = 0; nt < 16; nt++)
#pragma unroll
            for (int j = 0; j < 4; j++) acc[nt][j] = 0.0f;

        const float* Abuf = a_ptr0 + p * 1024;
        const float* ar0 = Abuf + g * 64;
        const float* ar1 = Abuf + (8 + g) * 64;
#pragma unroll
        for (int ks = 0; ks < 8; ks++) {
            int c0 = (((2 * ks)     ^ g) << 2) + t;
            int c1 = (((2 * ks + 1) ^ g) << 2) + t;
            uint32_t a0 = tf32r(ar0[c0]);
            uint32_t a1 = tf32r(ar1[c0]);
            uint32_t a2 = tf32r(ar0[c1]);
            uint32_t a3 = tf32r(ar1[c1]);
            const uint2* brow = B_s + ks * 512 + g * 4 + t;
#pragma unroll
            for (int nt = 0; nt < 16; nt++) {
                uint2 bv = brow[nt * 32];
                mma_tf32(acc[nt][0], acc[nt][1], acc[nt][2], acc[nt][3],
                         a0, a1, a2, a3, bv.x, bv.y);
            }
        }

        // epilogue: gather xW[src], ReLU, vector atomic scatter
#pragma unroll
        for (int rs = 0; rs < 2; rs++) {
            int s = rs ? s1 : s0;
            int d = rs ? d1 : d0;
            if ((unsigned)s >= (unsigned)N || (unsigned)d >= (unsigned)N) continue;
            const float* gp = &g_xw[(size_t)s * 128];
            float* op = &out[(size_t)d * 128];
#pragma unroll
            for (int q = 0; q < 8; q++) {
                int lc = q * 16 + 4 * t;
                float4 gv = *(const float4*)&gp[lc];
                float v0 = fmaxf(acc[2 * q    ][rs * 2    ] + gv.x, 0.f);
                float v1 = fmaxf(acc[2 * q    ][rs * 2 + 1] + gv.y, 0.f);
                float v2 = fmaxf(acc[2 * q + 1][rs * 2    ] + gv.z, 0.f);
                float v3 = fmaxf(acc[2 * q + 1][rs * 2 + 1] + gv.w, 0.f);
                red_add_v4(op + lc, v0, v1, v2, v3);
            }
        }
        p ^= 1;
    }
}

extern "C" void kernel_launch(void* const* d_in, const int* in_sizes, int n_in,
                              void* d_out, int out_size) {
    const float* x    = (const float*)d_in[0];
    const int*   eidx = (const int*)d_in[1];   // int32 [2][E]
    const float* ea   = (const float*)d_in[2];
    const float* W    = (const float*)d_in[3];
    const float* b    = (const float*)d_in[4];
    float* out = (float*)d_out;

    const int N = in_sizes[0] / 128;   // 50000
    const int E = in_sizes[2] / 64;    // 800000
    const int ntilesN = (N + 127) / 128;
    const int nwtiles = (E + 15) / 16;

    cudaFuncSetAttribute(node_fused_kernel,
                         cudaFuncAttributeMaxDynamicSharedMemorySize, NODE_SMEM);
    cudaFuncSetAttribute(edge_mma_kernel,
                         cudaFuncAttributeMaxDynamicSharedMemorySize, EDGE_SMEM);

    node_fused_kernel<<<NB_ZERO + ntilesN, 256, NODE_SMEM>>>(x, W, b, out, out_size, N, ntilesN);

    int grid = 296;
    edge_mma_kernel<<<grid, 256, EDGE_SMEM>>>(eidx, ea, W, out, E, N, nwtiles);
}

// round 9
// speedup vs baseline: 2.2440x; 1.0840x over previous
#include <cuda_runtime.h>
#include <cstdint>

#define MAX_NODES 50000
__device__ float g_xw[(size_t)MAX_NODES * 128];   // x @ W[64:192] + b (fp32)

// ---------------- helpers ----------------
__device__ __forceinline__ void red_add_v4(float* p, float a, float b, float c, float d) {
    asm volatile("red.global.add.v4.f32 [%0], {%1,%2,%3,%4};"
                 :: "l"(p), "f"(a), "f"(b), "f"(c), "f"(d) : "memory");
}
__device__ __forceinline__ uint32_t tf32r(float f) {
    uint32_t r; asm("cvt.rna.tf32.f32 %0, %1;" : "=r"(r) : "f"(f)); return r;
}
__device__ __forceinline__ uint32_t smem_u32(const void* p) {
    uint32_t a;
    asm("{ .reg .u64 t; cvta.to.shared.u64 t, %1; cvt.u32.u64 %0, t; }" : "=r"(a) : "l"(p));
    return a;
}
__device__ __forceinline__ void cp_async16(uint32_t dst, const void* src) {
    asm volatile("cp.async.cg.shared.global [%0], [%1], 16;" :: "r"(dst), "l"(src));
}
__device__ __forceinline__ void mma_tf32(float& c0, float& c1, float& c2, float& c3,
                                         uint32_t a0, uint32_t a1, uint32_t a2, uint32_t a3,
                                         uint32_t b0, uint32_t b1) {
    asm volatile("mma.sync.aligned.m16n8k8.row.col.f32.tf32.tf32.f32 "
                 "{%0,%1,%2,%3}, {%4,%5,%6,%7}, {%8,%9}, {%0,%1,%2,%3};"
                 : "+f"(c0), "+f"(c1), "+f"(c2), "+f"(c3)
                 : "r"(a0), "r"(a1), "r"(a2), "r"(a3), "r"(b0), "r"(b1));
}
__device__ __forceinline__ float4 ldg_v4(const float* p) {
    float4 v;
    asm volatile("ld.global.nc.v4.f32 {%0,%1,%2,%3}, [%4];"
                 : "=f"(v.x), "=f"(v.y), "=f"(v.z), "=f"(v.w) : "l"(p));
    return v;
}
// logical column for physical fragment column n (each thread's 4 cols contiguous)
__device__ __forceinline__ int colperm(int n) {
    int q = n & 15;
    return (q < 8) ? (n & ~15) + 4 * (q >> 1) + (q & 1)
                   : (n & ~15) + 4 * ((q - 8) >> 1) + 2 + (q & 1);
}

// ---------------------------------------------------------------------------
// Kernel A (fused): blocks [0,NB_ZERO) zero `out`; the rest run the node GEMM
// xW = x @ W[64:192] + b on mma.sync tf32 (K=128 = 2 phases of 64).
// ---------------------------------------------------------------------------
#define NB_ZERO  128
#define NA_OFF   65536
#define NBIAS_OFF 98304
#define NODE_SMEM (NBIAS_OFF + 512)

__global__ __launch_bounds__(256, 2)
void node_fused_kernel(const float* __restrict__ x,
                       const float* __restrict__ W,   // [192][128]
                       const float* __restrict__ b,
                       float* __restrict__ out, int out_n,
                       int N, int ntiles) {
    const int tid = threadIdx.x;

    if (blockIdx.x < NB_ZERO) {               // zero the output buffer
        float4 z = make_float4(0.f, 0.f, 0.f, 0.f);
        int total4 = out_n >> 2;
        for (int i = blockIdx.x * 256 + tid; i < total4; i += NB_ZERO * 256)
            ((float4*)out)[i] = z;
        return;
    }

    extern __shared__ char smem[];
    const uint32_t sb = smem_u32(smem);
    uint2* B_s   = (uint2*)smem;
    float* bias_s = (float*)(smem + NBIAS_OFF);

    const int wid  = tid >> 5, lane = tid & 31;
    const int g    = lane >> 2, t = lane & 3;
    const int wbase = wid * 16;
    const int tile = blockIdx.x - NB_ZERO;
    if (tile >= ntiles) return;
    const int n0 = tile * 128;

    // build B fragments from W rows [64,192): 8192 uint2 entries
#pragma unroll
    for (int it = 0; it < 32; it++) {
        int i = tid + it * 256;
        int c = i & 3, n = (i >> 2) & 127, ks = i >> 9;
        int l = colperm(n);
        int k0 = 64 + ks * 8 + c;
        B_s[i] = make_uint2(tf32r(W[(size_t)k0 * 128 + l]),
                            tf32r(W[(size_t)(k0 + 4) * 128 + l]));
    }
    if (tid < 128) bias_s[tid] = b[tid];

    float acc[16][4];
#pragma unroll
    for (int nt = 0; nt < 16; nt++)
#pragma unroll
        for (int j = 0; j < 4; j++) acc[nt][j] = 0.0f;

    for (int h = 0; h < 2; h++) {
#pragma unroll
        for (int it = 0; it < 8; it++) {
            int i = tid + it * 256;
            int e = i >> 4, q = i & 15;
            int n = n0 + e; if (n > N - 1) n = N - 1;
            uint32_t dst = sb + NA_OFF + e * 256 + ((q ^ (e & 7)) << 4);
            cp_async16(dst, x + (size_t)n * 128 + h * 64 + q * 4);
        }
        asm volatile("cp.async.commit_group;" ::: "memory");
        asm volatile("cp.async.wait_group 0;" ::: "memory");
        __syncthreads();

        const float* Abuf = (const float*)(smem + NA_OFF);
        const float* ar0 = Abuf + (wbase + g) * 64;
        const float* ar1 = Abuf + (wbase + 8 + g) * 64;
#pragma unroll
        for (int ks = 0; ks < 8; ks++) {
            int c0 = (((2 * ks)     ^ g) << 2) + t;
            int c1 = (((2 * ks + 1) ^ g) << 2) + t;
            uint32_t a0 = tf32r(ar0[c0]);
            uint32_t a1 = tf32r(ar1[c0]);
            uint32_t a2 = tf32r(ar0[c1]);
            uint32_t a3 = tf32r(ar1[c1]);
            const uint2* brow = B_s + (h * 8 + ks) * 512 + g * 4 + t;
#pragma unroll
            for (int nt = 0; nt < 16; nt++) {
                uint2 bv = brow[nt * 32];
                mma_tf32(acc[nt][0], acc[nt][1], acc[nt][2], acc[nt][3],
                         a0, a1, a2, a3, bv.x, bv.y);
            }
        }
        if (h == 0) __syncthreads();   // A buffer reused for half 1
    }

    // epilogue: add bias, store fp32 rows of g_xw
#pragma unroll
    for (int rs = 0; rs < 2; rs++) {
        int m = wbase + g + 8 * rs;
        int n = n0 + m;
        if (n >= N) continue;
        float* p = &g_xw[(size_t)n * 128];
#pragma unroll
        for (int q = 0; q < 8; q++) {
            int lc = q * 16 + 4 * t;
            float4 bv = *(const float4*)&bias_s[lc];
            float4 v = make_float4(acc[2 * q    ][rs * 2    ] + bv.x,
                                   acc[2 * q    ][rs * 2 + 1] + bv.y,
                                   acc[2 * q + 1][rs * 2    ] + bv.z,
                                   acc[2 * q + 1][rs * 2 + 1] + bv.w);
            *(float4*)&p[lc] = v;
        }
    }
}

// ---------------------------------------------------------------------------
// Kernel B: warp-autonomous edge pipeline, 384 threads (12 warps), 1 CTA/SM.
// Gather xW[src] prefetched into REGISTERS before the MMA loop (latency hides
// under 128 HMMAs). B fragments packed as uint4 (2 n-tiles per LDS.128).
// smem: B @0 (32KB) | warp w: A bufs 2x4KB @ 32768 + w*8192
// ---------------------------------------------------------------------------
#define AW_OFF  32768
#define EDGE_SMEM (AW_OFF + 12 * 8192)   // 131072

__global__ __launch_bounds__(384, 1)
void edge_mma_kernel(const int* __restrict__ eidx,   // [2][E] int32
                     const float* __restrict__ ea,   // [E][64]
                     const float* __restrict__ W,    // [192][128]
                     float* __restrict__ out,        // [N][128]
                     int E, int N, int nwtiles) {
    extern __shared__ char smem[];
    const uint32_t sb = smem_u32(smem);
    uint2* B2 = (uint2*)smem;
    const uint4* B4 = (const uint4*)smem;

    const int tid  = threadIdx.x;
    const int wid  = tid >> 5, lane = tid & 31;
    const int g    = lane >> 2, t = lane & 3;
    const int tp   = g * 4 + t;

    // build B fragments from W rows [0,64), paired layout:
    // uint4 j = ks*256 + (nt>>1)*32 + tp holds frags for nt=2p (xy), nt=2p+1 (zw)
    for (int i = tid; i < 8192; i += 384) {
        int c = i & 3, n = (i >> 2) & 127, ks = i >> 9;
        int l = colperm(n);
        int k0 = ks * 8 + c;
        uint2 v = make_uint2(tf32r(W[(size_t)k0 * 128 + l]),
                             tf32r(W[(size_t)(k0 + 4) * 128 + l]));
        int nt = n >> 3, gg = n & 7;
        int i2 = ks * 512 + (nt >> 1) * 64 + (gg * 4 + c) * 2 + (nt & 1);
        B2[i2] = v;
    }
    __syncthreads();

    const uint32_t a_base = sb + AW_OFF + wid * 8192;
    const float*   a_ptr0 = (const float*)(smem + AW_OFF + wid * 8192);

    auto issue = [&](int wt2, int p2) {
        size_t ebase = (size_t)wt2 * 16;
#pragma unroll
        for (int it = 0; it < 8; it++) {
            int i = lane + it * 32;          // 256 16B chunks
            int e = i >> 4, q = i & 15;
            size_t se = ebase + e;
            if (se > (size_t)E - 1) se = (size_t)E - 1;
            cp_async16(a_base + p2 * 4096 + e * 256 + ((q ^ (e & 7)) << 4),
                       ea + se * 64 + q * 4);
        }
        asm volatile("cp.async.commit_group;" ::: "memory");
    };

    const int stride = gridDim.x * 12;
    int wt = blockIdx.x * 12 + wid;
    int p = 0;
    int s0 = -1, d0 = -1, s1 = -1, d1 = -1;
    if (wt < nwtiles) {
        issue(wt, 0);
        size_t ebase = (size_t)wt * 16;
        if (ebase + g < (size_t)E) {
            s0 = eidx[ebase + g];
            d0 = eidx[(size_t)E + ebase + g];
        }
        if (ebase + g + 8 < (size_t)E) {
            s1 = eidx[ebase + g + 8];
            d1 = eidx[(size_t)E + ebase + g + 8];
        }
    }

    for (; wt < nwtiles; wt += stride) {
        // (a) gather prefetch into registers (independent of MMA result)
        int ss0 = ((unsigned)s0 < (unsigned)N) ? s0 : 0;
        int ss1 = ((unsigned)s1 < (unsigned)N) ? s1 : 0;
        float4 gv0[8], gv1[8];
        {
            const float* gp0 = g_xw + (size_t)ss0 * 128 + 4 * t;
            const float* gp1 = g_xw + (size_t)ss1 * 128 + 4 * t;
#pragma unroll
            for (int q = 0; q < 8; q++) gv0[q] = ldg_v4(gp0 + q * 16);
#pragma unroll
            for (int q = 0; q < 8; q++) gv1[q] = ldg_v4(gp1 + q * 16);
        }

        // (b) issue next A tile, (c) prefetch next indices
        int next = wt + stride;
        int ns0 = -1, nd0 = -1, ns1 = -1, nd1 = -1;
        __syncwarp();
        if (next < nwtiles) {
            issue(next, p ^ 1);
            size_t nb = (size_t)next * 16;
            if (nb + g < (size_t)E) {
                ns0 = eidx[nb + g];
                nd0 = eidx[(size_t)E + nb + g];
            }
            if (nb + g + 8 < (size_t)E) {
                ns1 = eidx[nb + g + 8];
                nd1 = eidx[(size_t)E + nb + g + 8];
            }
            asm volatile("cp.async.wait_group 1;" ::: "memory");
        } else {
            asm volatile("cp.async.wait_group 0;" ::: "memory");
        }
        __syncwarp();

        // (e) MMA from buffer p
        float acc[16][4];
#pragma unroll
        for (int nt = 0; nt < 16; nt++)
#pragma unroll
            for (int j = 0; j < 4; j++) acc[nt][j] = 0.0f;

        const float* Abuf = a_ptr0 + p * 1024;
        const float* ar0 = Abuf + g * 64;
        const float* ar1 = Abuf + (8 + g) * 64;
#pragma unroll
        for (int ks = 0; ks < 8; ks++) {
            int c0 = (((2 * ks)     ^ g) << 2) + t;
            int c1 = (((2 * ks + 1) ^ g) << 2) + t;
            uint32_t a0 = tf32r(ar0[c0]);
            uint32_t a1 = tf32r(ar1[c0]);
            uint32_t a2 = tf32r(ar0[c1]);
            uint32_t a3 = tf32r(ar1[c1]);
            const uint4* b4 = B4 + ks * 256 + tp;
#pragma unroll
            for (int pp = 0; pp < 8; pp++) {
                uint4 bw = b4[pp * 32];
                mma_tf32(acc[2 * pp    ][0], acc[2 * pp    ][1],
                         acc[2 * pp    ][2], acc[2 * pp    ][3],
                         a0, a1, a2, a3, bw.x, bw.y);
                mma_tf32(acc[2 * pp + 1][0], acc[2 * pp + 1][1],
                         acc[2 * pp + 1][2], acc[2 * pp + 1][3],
                         a0, a1, a2, a3, bw.z, bw.w);
            }
        }

        // (f) epilogue: ReLU(acc + gathered) -> vector atomic scatter
        size_t ebase = (size_t)wt * 16;
#pragma unroll
        for (int rs = 0; rs < 2; rs++) {
            int d = rs ? d1 : d0;
            int m = g + 8 * rs;
            if (ebase + m >= (size_t)E || (unsigned)d >= (unsigned)N) continue;
            float* op = &out[(size_t)d * 128];
            float4* gvp = rs ? gv1 : gv0;
#pragma unroll
            for (int q = 0; q < 8; q++) {
                int lc = q * 16 + 4 * t;
                float4 gvv = gvp[q];
                float v0 = fmaxf(acc[2 * q    ][rs * 2    ] + gvv.x, 0.f);
                float v1 = fmaxf(acc[2 * q    ][rs * 2 + 1] + gvv.y, 0.f);
                float v2 = fmaxf(acc[2 * q + 1][rs * 2    ] + gvv.z, 0.f);
                float v3 = fmaxf(acc[2 * q + 1][rs * 2 + 1] + gvv.w, 0.f);
                red_add_v4(op + lc, v0, v1, v2, v3);
            }
        }
        s0 = ns0; d0 = nd0; s1 = ns1; d1 = nd1;
        p ^= 1;
    }
}

extern "C" void kernel_launch(void* const* d_in, const int* in_sizes, int n_in,
                              void* d_out, int out_size) {
    const float* x    = (const float*)d_in[0];
    const int*   eidx = (const int*)d_in[1];   // int32 [2][E]
    const float* ea   = (const float*)d_in[2];
    const float* W    = (const float*)d_in[3];
    const float* b    = (const float*)d_in[4];
    float* out = (float*)d_out;

    const int N = in_sizes[0] / 128;   // 50000
    const int E = in_sizes[2] / 64;    // 800000
    const int ntilesN = (N + 127) / 128;
    const int nwtiles = (E + 15) / 16;

    cudaFuncSetAttribute(node_fused_kernel,
                         cudaFuncAttributeMaxDynamicSharedMemorySize, NODE_SMEM);
    cudaFuncSetAttribute(edge_mma_kernel,
                         cudaFuncAttributeMaxDynamicSharedMemorySize, EDGE_SMEM);

    node_fused_kernel<<<NB_ZERO + ntilesN, 256, NODE_SMEM>>>(x, W, b, out, out_size, N, ntilesN);

    edge_mma_kernel<<<148, 384, EDGE_SMEM>>>(eidx, ea, W, out, E, N, nwtiles);
}